// round 15
// baseline (speedup 1.0000x reference)
#include <cuda_runtime.h>
#include <cuda_bf16.h>
#include <math.h>

// Problem constants (fixed by the reference)
#define NN 60000
#define EE 240000
#define FIN 10
#define SS 3
#define CC 16
#define GG 512

// ---------------- device scratch (no allocations allowed) ----------------
__device__ int    g_cnt[NN];
__device__ int    g_rowptr[NN + 1];
__device__ int    g_cursor[NN];
__device__ int    g_col[EE];
__device__ float4 g_ef[EE];            // (a_val, e0, e1, e2) sorted by row
__device__ float  g_xw1[NN * 16];      // x @ W_gcn1
__device__ float  g_g1 [NN * 16];      // GCN layer-1 output
__device__ float  g_xw2[NN * 32];      // g1 @ W_gcn2
__device__ float  g_U1 [NN * 64];      // [n][s][16]: s=0 -> x@Be1, s=1..3 -> x@We1_s
__device__ float  g_c1 [NN * 16];      // ECC layer-1 output
__device__ float  g_U2 [NN * 128];     // [n][s][32]: s=0 -> c1@Be2, s=1..3 -> c1@We2_s
__device__ float  g_pool[GG * 64];     // [g][0:32]=p1 (GCN), [g][32:64]=p2 (ECC)

// ---------------- CSR build ----------------
__global__ void k_zero() {
    int i = blockIdx.x * blockDim.x + threadIdx.x;
    if (i < NN) g_cnt[i] = 0;
    if (i < GG * 64) g_pool[i] = 0.f;
}

__global__ void k_count(const int* __restrict__ ei) {
    int e = blockIdx.x * blockDim.x + threadIdx.x;
    if (e >= EE) return;
    atomicAdd(&g_cnt[ei[e]], 1);   // rows = ei[0..E)
}

__global__ void k_scan() {
    __shared__ int ssum[1024];
    const int CH = (NN + 1023) / 1024;
    int t = threadIdx.x;
    int start = t * CH;
    int end = min(start + CH, NN);
    int s = 0;
    for (int i = start; i < end; i++) s += g_cnt[i];
    ssum[t] = s;
    __syncthreads();
    int local = s;
    for (int off = 1; off < 1024; off <<= 1) {
        int tmp = (t >= off) ? ssum[t - off] : 0;
        __syncthreads();
        ssum[t] += tmp;
        __syncthreads();
    }
    int run = ssum[t] - local;   // exclusive prefix for this chunk
    for (int i = start; i < end; i++) {
        g_rowptr[i] = run;
        g_cursor[i] = run;
        run += g_cnt[i];
    }
    if (t == 1023) g_rowptr[NN] = ssum[1023];
}

__global__ void k_scatter(const int* __restrict__ ei,
                          const float* __restrict__ a_vals,
                          const float* __restrict__ efeat) {
    int e = blockIdx.x * blockDim.x + threadIdx.x;
    if (e >= EE) return;
    int r = ei[e];
    int c = ei[EE + e];
    int pos = atomicAdd(&g_cursor[r], 1);
    g_col[pos] = c;
    g_ef[pos] = make_float4(a_vals[e], efeat[e * 3], efeat[e * 3 + 1], efeat[e * 3 + 2]);
}

// ---------------- node transforms ----------------
// layer-1: per node, 80 outputs: o<16 -> xw1 ; o in [16,80) -> U1 blocks (Be1, We1_0..2)
__global__ void k_nt1(const float* __restrict__ x,
                      const float* __restrict__ Wg1,
                      const float* __restrict__ We1,
                      const float* __restrict__ be1) {
    int tid = blockIdx.x * blockDim.x + threadIdx.x;
    int n = tid / 80;
    int o = tid - n * 80;
    if (n >= NN) return;
    const float* xr = x + n * FIN;
    float acc = 0.f;
    if (o < 16) {
        #pragma unroll
        for (int f = 0; f < FIN; f++) acc += xr[f] * __ldg(&Wg1[f * 16 + o]);
        g_xw1[n * 16 + o] = acc;
    } else {
        int idx = o - 16;
        int s = idx >> 4;
        int oo = idx & 15;
        const float* w = (s == 0) ? be1 : (We1 + (s - 1) * (FIN * 16));
        #pragma unroll
        for (int f = 0; f < FIN; f++) acc += xr[f] * __ldg(&w[f * 16 + oo]);
        g_U1[n * 64 + idx] = acc;
    }
}

// layer-2: per node, 160 outputs: o<32 -> xw2 (from g1) ; o in [32,160) -> U2 (from c1)
__global__ void k_nt2(const float* __restrict__ Wg2,
                      const float* __restrict__ We2,
                      const float* __restrict__ be2) {
    int tid = blockIdx.x * blockDim.x + threadIdx.x;
    int n = tid / 160;
    int o = tid - n * 160;
    if (n >= NN) return;
    float acc = 0.f;
    if (o < 32) {
        const float* src = g_g1 + n * 16;
        #pragma unroll
        for (int f = 0; f < 16; f++) acc += src[f] * __ldg(&Wg2[f * 32 + o]);
        g_xw2[n * 32 + o] = acc;
    } else {
        int idx = o - 32;
        int s = idx >> 5;
        int oo = idx & 31;
        const float* w = (s == 0) ? be2 : (We2 + (s - 1) * (16 * 32));
        const float* src = g_c1 + n * 16;
        #pragma unroll
        for (int f = 0; f < 16; f++) acc += src[f] * __ldg(&w[f * 32 + oo]);
        g_U2[n * 128 + idx] = acc;
    }
}

// ---------------- aggregations ----------------
// GCN layer 1: 16 lanes/node, out g1
__global__ void k_gcn1(const float* __restrict__ b1) {
    int tid = blockIdx.x * blockDim.x + threadIdx.x;
    int n = tid >> 4;
    int lane = tid & 15;
    if (n >= NN) return;
    int beg = g_rowptr[n], end = g_rowptr[n + 1];
    float acc = 0.f;
    for (int j = beg; j < end; j++) {
        int c = g_col[j];
        float a = g_ef[j].x;
        acc += a * g_xw1[c * 16 + lane];
    }
    g_g1[n * 16 + lane] = fmaxf(acc + __ldg(&b1[lane]), 0.f);
}

// ECC layer 1: 16 lanes/node, out c1 (includes root term + bias + relu)
__global__ void k_ecc1(const float* __restrict__ x,
                       const float* __restrict__ root1,
                       const float* __restrict__ bias1) {
    int tid = blockIdx.x * blockDim.x + threadIdx.x;
    int n = tid >> 4;
    int lane = tid & 15;
    if (n >= NN) return;
    int beg = g_rowptr[n], end = g_rowptr[n + 1];
    float acc = 0.f;
    for (int j = beg; j < end; j++) {
        int c = g_col[j];
        float4 f = g_ef[j];
        const float* u = g_U1 + c * 64;
        acc += u[lane] + f.y * u[16 + lane] + f.z * u[32 + lane] + f.w * u[48 + lane];
    }
    float rt = 0.f;
    const float* xr = x + n * FIN;
    #pragma unroll
    for (int f = 0; f < FIN; f++) rt += xr[f] * __ldg(&root1[f * 16 + lane]);
    g_c1[n * 16 + lane] = fmaxf(acc + rt + __ldg(&bias1[lane]), 0.f);
}

// GCN layer 2 fused with pooling: 32 lanes/node, atomicAdd into pool[:,0:32]
__global__ void k_gcn2_pool(const float* __restrict__ b2,
                            const int* __restrict__ seg) {
    int tid = blockIdx.x * blockDim.x + threadIdx.x;
    int n = tid >> 5;
    int lane = tid & 31;
    if (n >= NN) return;
    int beg = g_rowptr[n], end = g_rowptr[n + 1];
    float acc = 0.f;
    for (int j = beg; j < end; j++) {
        int c = g_col[j];
        float a = g_ef[j].x;
        acc += a * g_xw2[c * 32 + lane];
    }
    float v = fmaxf(acc + __ldg(&b2[lane]), 0.f);
    atomicAdd(&g_pool[seg[n] * 64 + lane], v);
}

// ECC layer 2 fused with pooling: 32 lanes/node, atomicAdd into pool[:,32:64]
__global__ void k_ecc2_pool(const float* __restrict__ root2,
                            const float* __restrict__ bias2,
                            const int* __restrict__ seg) {
    int tid = blockIdx.x * blockDim.x + threadIdx.x;
    int n = tid >> 5;
    int lane = tid & 31;
    if (n >= NN) return;
    int beg = g_rowptr[n], end = g_rowptr[n + 1];
    float acc = 0.f;
    for (int j = beg; j < end; j++) {
        int c = g_col[j];
        float4 f = g_ef[j];
        const float* u = g_U2 + c * 128;
        acc += u[lane] + f.y * u[32 + lane] + f.z * u[64 + lane] + f.w * u[96 + lane];
    }
    float rt = 0.f;
    const float* cr = g_c1 + n * 16;
    #pragma unroll
    for (int f = 0; f < 16; f++) rt += cr[f] * __ldg(&root2[f * 32 + lane]);
    float v = fmaxf(acc + rt + __ldg(&bias2[lane]), 0.f);
    atomicAdd(&g_pool[seg[n] * 64 + 32 + lane], v);
}

// ---------------- MLP head ----------------
__global__ void k_head(const float* __restrict__ Wd1, const float* __restrict__ bd1,
                       const float* __restrict__ Wd2, const float* __restrict__ bd2,
                       const float* __restrict__ Wo,  const float* __restrict__ bo,
                       float* __restrict__ out) {
    int g = blockIdx.x * blockDim.x + threadIdx.x;
    if (g >= GG) return;
    float h[64];
    #pragma unroll
    for (int k = 0; k < 64; k++) h[k] = g_pool[g * 64 + k];
    float t1[16];
    #pragma unroll
    for (int c = 0; c < 16; c++) {
        float acc = __ldg(&bd1[c]);
        #pragma unroll
        for (int k = 0; k < 64; k++) acc += h[k] * __ldg(&Wd1[k * 16 + c]);
        t1[c] = fmaxf(acc, 0.f);
    }
    float t2[8];
    #pragma unroll
    for (int c = 0; c < 8; c++) {
        float acc = __ldg(&bd2[c]);
        #pragma unroll
        for (int k = 0; k < 16; k++) acc += t1[k] * __ldg(&Wd2[k * 8 + c]);
        t2[c] = fmaxf(acc, 0.f);
    }
    float o = __ldg(&bo[0]);
    #pragma unroll
    for (int k = 0; k < 8; k++) o += t2[k] * __ldg(&Wo[k]);
    out[g] = 1.f / (1.f + expf(-o));
}

// ---------------- launch ----------------
extern "C" void kernel_launch(void* const* d_in, const int* in_sizes, int n_in,
                              void* d_out, int out_size) {
    const float* x      = (const float*)d_in[0];
    const float* a_vals = (const float*)d_in[1];
    const float* efeat  = (const float*)d_in[2];
    const int*   ei     = (const int*)  d_in[3];
    const int*   seg    = (const int*)  d_in[4];
    const float* Wg1    = (const float*)d_in[5];
    const float* b1     = (const float*)d_in[6];
    const float* Wg2    = (const float*)d_in[7];
    const float* b2     = (const float*)d_in[8];
    const float* We1    = (const float*)d_in[9];
    const float* be1    = (const float*)d_in[10];
    const float* root1  = (const float*)d_in[11];
    const float* bias1  = (const float*)d_in[12];
    const float* We2    = (const float*)d_in[13];
    const float* be2    = (const float*)d_in[14];
    const float* root2  = (const float*)d_in[15];
    const float* bias2  = (const float*)d_in[16];
    const float* Wd1    = (const float*)d_in[17];
    const float* bd1    = (const float*)d_in[18];
    const float* Wd2    = (const float*)d_in[19];
    const float* bd2    = (const float*)d_in[20];
    const float* Wo     = (const float*)d_in[21];
    const float* bo     = (const float*)d_in[22];
    float* out = (float*)d_out;

    const int B = 256;

    // CSR build
    k_zero   <<<(NN + B - 1) / B, B>>>();
    k_count  <<<(EE + B - 1) / B, B>>>(ei);
    k_scan   <<<1, 1024>>>();
    k_scatter<<<(EE + B - 1) / B, B>>>(ei, a_vals, efeat);

    // layer-1 node transforms (xw1, U1)
    k_nt1<<<(NN * 80 + B - 1) / B, B>>>(x, Wg1, We1, be1);

    // layer-1 aggregations
    k_gcn1<<<(NN * 16 + B - 1) / B, B>>>(b1);
    k_ecc1<<<(NN * 16 + B - 1) / B, B>>>(x, root1, bias1);

    // layer-2 node transforms (xw2, U2)
    k_nt2<<<(NN * 160 + B - 1) / B, B>>>(Wg2, We2, be2);

    // layer-2 aggregations fused with graph pooling
    k_gcn2_pool<<<(NN * 32 + B - 1) / B, B>>>(b2, seg);
    k_ecc2_pool<<<(NN * 32 + B - 1) / B, B>>>(root2, bias2, seg);

    // MLP head
    k_head<<<(GG + B - 1) / B, B>>>(Wd1, bd1, Wd2, bd2, Wo, bo, out);
}

// round 16
// speedup vs baseline: 1.0320x; 1.0320x over previous
#include <cuda_runtime.h>
#include <cuda_bf16.h>
#include <math.h>

#define NN 60000
#define EE 240000
#define FIN 10
#define SS 3
#define CC 16
#define GG 512

// ---------------- device scratch ----------------
__device__ int    g_cnt[NN];
__device__ int    g_rowptr[NN + 1];
__device__ int    g_cursor[NN];
__device__ int    g_col[EE];
__device__ float4 g_ef[EE];            // (a_val, e0, e1, e2) sorted by row
__device__ float  g_xw1[NN * 16];      // x @ W_gcn1
__device__ float  g_g1 [NN * 16];      // GCN layer-1 output
__device__ float  g_xw2[NN * 32];      // g1 @ W_gcn2
__device__ float  g_U1 [NN * 64];      // [n][s][16]
__device__ float  g_c1 [NN * 16];      // ECC layer-1 output
__device__ float  g_U2 [NN * 128];     // [n][s][32]
__device__ float  g_pool[GG * 64];     // [g][0:32]=GCN pool, [g][32:64]=ECC pool

// ---------------- init: zero cnt + pool ----------------
__global__ void k_init() {
    int i = blockIdx.x * blockDim.x + threadIdx.x;
    if (i < NN) g_cnt[i] = 0;
    if (i < GG * 64) g_pool[i] = 0.f;
}

// ---------------- fused: edge count + layer-1 node transforms ----------------
// blocks [0, CB): count rows.  blocks [CB, CB+NB): nt1 (xw1 + U1).
__global__ void k_count_nt1(const int* __restrict__ ei,
                            const float* __restrict__ x,
                            const float* __restrict__ Wg1,
                            const float* __restrict__ We1,
                            const float* __restrict__ be1,
                            int CB) {
    if (blockIdx.x < CB) {
        int e = blockIdx.x * blockDim.x + threadIdx.x;
        if (e < EE) atomicAdd(&g_cnt[ei[e]], 1);
        return;
    }
    int tid = (blockIdx.x - CB) * blockDim.x + threadIdx.x;
    int n = tid / 80;
    int o = tid - n * 80;
    if (n >= NN) return;
    const float* xr = x + n * FIN;
    float acc = 0.f;
    if (o < 16) {
        #pragma unroll
        for (int f = 0; f < FIN; f++) acc += xr[f] * __ldg(&Wg1[f * 16 + o]);
        g_xw1[n * 16 + o] = acc;
    } else {
        int idx = o - 16;
        int s = idx >> 4;
        int oo = idx & 15;
        const float* w = (s == 0) ? be1 : (We1 + (s - 1) * (FIN * 16));
        #pragma unroll
        for (int f = 0; f < FIN; f++) acc += xr[f] * __ldg(&w[f * 16 + oo]);
        g_U1[n * 64 + idx] = acc;
    }
}

// ---------------- single-block scan ----------------
__global__ void k_scan() {
    __shared__ int ssum[1024];
    const int CH = (NN + 1023) / 1024;
    int t = threadIdx.x;
    int start = t * CH;
    int end = min(start + CH, NN);
    int s = 0;
    for (int i = start; i < end; i++) s += g_cnt[i];
    ssum[t] = s;
    __syncthreads();
    int local = s;
    for (int off = 1; off < 1024; off <<= 1) {
        int tmp = (t >= off) ? ssum[t - off] : 0;
        __syncthreads();
        ssum[t] += tmp;
        __syncthreads();
    }
    int run = ssum[t] - local;
    for (int i = start; i < end; i++) {
        g_rowptr[i] = run;
        g_cursor[i] = run;
        run += g_cnt[i];
    }
    if (t == 1023) g_rowptr[NN] = ssum[1023];
}

__global__ void k_scatter(const int* __restrict__ ei,
                          const float* __restrict__ a_vals,
                          const float* __restrict__ efeat) {
    int e = blockIdx.x * blockDim.x + threadIdx.x;
    if (e >= EE) return;
    int r = ei[e];
    int c = ei[EE + e];
    int pos = atomicAdd(&g_cursor[r], 1);
    g_col[pos] = c;
    g_ef[pos] = make_float4(a_vals[e], efeat[e * 3], efeat[e * 3 + 1], efeat[e * 3 + 2]);
}

// ---------------- fused layer-1 aggregation (GCN1 + ECC1) ----------------
// 16 lanes/node; each lane accumulates gcn1[lane] and ecc1[lane] in one edge walk.
__global__ void k_agg1(const float* __restrict__ x,
                       const float* __restrict__ b1,
                       const float* __restrict__ root1,
                       const float* __restrict__ bias1) {
    int tid = blockIdx.x * blockDim.x + threadIdx.x;
    int n = tid >> 4;
    int lane = tid & 15;
    if (n >= NN) return;
    int beg = g_rowptr[n], end = g_rowptr[n + 1];
    float ag = 0.f, ae = 0.f;
    int j = beg;
    // 2-way unrolled: two edges' gathers in flight
    for (; j + 1 < end; j += 2) {
        int c0 = g_col[j], c1 = g_col[j + 1];
        float4 f0 = g_ef[j], f1 = g_ef[j + 1];
        const float* u0 = g_U1 + (size_t)c0 * 64;
        const float* u1 = g_U1 + (size_t)c1 * 64;
        float x0 = g_xw1[(size_t)c0 * 16 + lane];
        float x1 = g_xw1[(size_t)c1 * 16 + lane];
        float v00 = u0[lane],      v01 = u0[16 + lane], v02 = u0[32 + lane], v03 = u0[48 + lane];
        float v10 = u1[lane],      v11 = u1[16 + lane], v12 = u1[32 + lane], v13 = u1[48 + lane];
        ag += f0.x * x0 + f1.x * x1;
        ae += v00 + f0.y * v01 + f0.z * v02 + f0.w * v03;
        ae += v10 + f1.y * v11 + f1.z * v12 + f1.w * v13;
    }
    if (j < end) {
        int c = g_col[j];
        float4 f = g_ef[j];
        const float* u = g_U1 + (size_t)c * 64;
        ag += f.x * g_xw1[(size_t)c * 16 + lane];
        ae += u[lane] + f.y * u[16 + lane] + f.z * u[32 + lane] + f.w * u[48 + lane];
    }
    float rt = 0.f;
    const float* xr = x + n * FIN;
    #pragma unroll
    for (int f = 0; f < FIN; f++) rt += xr[f] * __ldg(&root1[f * 16 + lane]);
    g_g1[n * 16 + lane] = fmaxf(ag + __ldg(&b1[lane]), 0.f);
    g_c1[n * 16 + lane] = fmaxf(ae + rt + __ldg(&bias1[lane]), 0.f);
}

// ---------------- layer-2 node transforms ----------------
__global__ void k_nt2(const float* __restrict__ Wg2,
                      const float* __restrict__ We2,
                      const float* __restrict__ be2) {
    int tid = blockIdx.x * blockDim.x + threadIdx.x;
    int n = tid / 160;
    int o = tid - n * 160;
    if (n >= NN) return;
    float acc = 0.f;
    if (o < 32) {
        const float* src = g_g1 + n * 16;
        #pragma unroll
        for (int f = 0; f < 16; f++) acc += src[f] * __ldg(&Wg2[f * 32 + o]);
        g_xw2[n * 32 + o] = acc;
    } else {
        int idx = o - 32;
        int s = idx >> 5;
        int oo = idx & 31;
        const float* w = (s == 0) ? be2 : (We2 + (s - 1) * (16 * 32));
        const float* src = g_c1 + n * 16;
        #pragma unroll
        for (int f = 0; f < 16; f++) acc += src[f] * __ldg(&w[f * 32 + oo]);
        g_U2[n * 128 + idx] = acc;
    }
}

// ---------------- fused layer-2 aggregation + pooling (GCN2 + ECC2) ----------------
// 32 lanes/node; each lane accumulates gcn2[lane] and ecc2[lane]; atomics into pool.
__global__ void k_agg2_pool(const float* __restrict__ b2,
                            const float* __restrict__ root2,
                            const float* __restrict__ bias2,
                            const int* __restrict__ seg) {
    int tid = blockIdx.x * blockDim.x + threadIdx.x;
    int n = tid >> 5;
    int lane = tid & 31;
    if (n >= NN) return;
    int beg = g_rowptr[n], end = g_rowptr[n + 1];
    float ag = 0.f, ae = 0.f;
    int j = beg;
    for (; j + 1 < end; j += 2) {
        int c0 = g_col[j], c1 = g_col[j + 1];
        float4 f0 = g_ef[j], f1 = g_ef[j + 1];
        const float* u0 = g_U2 + (size_t)c0 * 128;
        const float* u1 = g_U2 + (size_t)c1 * 128;
        float x0 = g_xw2[(size_t)c0 * 32 + lane];
        float x1 = g_xw2[(size_t)c1 * 32 + lane];
        float v00 = u0[lane],      v01 = u0[32 + lane], v02 = u0[64 + lane], v03 = u0[96 + lane];
        float v10 = u1[lane],      v11 = u1[32 + lane], v12 = u1[64 + lane], v13 = u1[96 + lane];
        ag += f0.x * x0 + f1.x * x1;
        ae += v00 + f0.y * v01 + f0.z * v02 + f0.w * v03;
        ae += v10 + f1.y * v11 + f1.z * v12 + f1.w * v13;
    }
    if (j < end) {
        int c = g_col[j];
        float4 f = g_ef[j];
        const float* u = g_U2 + (size_t)c * 128;
        ag += f.x * g_xw2[(size_t)c * 32 + lane];
        ae += u[lane] + f.y * u[32 + lane] + f.z * u[64 + lane] + f.w * u[96 + lane];
    }
    float rt = 0.f;
    const float* cr = g_c1 + n * 16;
    #pragma unroll
    for (int f = 0; f < 16; f++) rt += cr[f] * __ldg(&root2[f * 32 + lane]);
    float vg = fmaxf(ag + __ldg(&b2[lane]), 0.f);
    float ve = fmaxf(ae + rt + __ldg(&bias2[lane]), 0.f);
    int gidx = seg[n] * 64;
    atomicAdd(&g_pool[gidx + lane], vg);
    atomicAdd(&g_pool[gidx + 32 + lane], ve);
}

// ---------------- MLP head ----------------
__global__ void k_head(const float* __restrict__ Wd1, const float* __restrict__ bd1,
                       const float* __restrict__ Wd2, const float* __restrict__ bd2,
                       const float* __restrict__ Wo,  const float* __restrict__ bo,
                       float* __restrict__ out) {
    int g = blockIdx.x * blockDim.x + threadIdx.x;
    if (g >= GG) return;
    float h[64];
    #pragma unroll
    for (int k = 0; k < 64; k++) h[k] = g_pool[g * 64 + k];
    float t1[16];
    #pragma unroll
    for (int c = 0; c < 16; c++) {
        float acc = __ldg(&bd1[c]);
        #pragma unroll
        for (int k = 0; k < 64; k++) acc += h[k] * __ldg(&Wd1[k * 16 + c]);
        t1[c] = fmaxf(acc, 0.f);
    }
    float t2[8];
    #pragma unroll
    for (int c = 0; c < 8; c++) {
        float acc = __ldg(&bd2[c]);
        #pragma unroll
        for (int k = 0; k < 16; k++) acc += t1[k] * __ldg(&Wd2[k * 8 + c]);
        t2[c] = fmaxf(acc, 0.f);
    }
    float o = __ldg(&bo[0]);
    #pragma unroll
    for (int k = 0; k < 8; k++) o += t2[k] * __ldg(&Wo[k]);
    out[g] = 1.f / (1.f + expf(-o));
}

// ---------------- launch ----------------
extern "C" void kernel_launch(void* const* d_in, const int* in_sizes, int n_in,
                              void* d_out, int out_size) {
    const float* x      = (const float*)d_in[0];
    const float* a_vals = (const float*)d_in[1];
    const float* efeat  = (const float*)d_in[2];
    const int*   ei     = (const int*)  d_in[3];
    const int*   seg    = (const int*)  d_in[4];
    const float* Wg1    = (const float*)d_in[5];
    const float* b1     = (const float*)d_in[6];
    const float* Wg2    = (const float*)d_in[7];
    const float* b2     = (const float*)d_in[8];
    const float* We1    = (const float*)d_in[9];
    const float* be1    = (const float*)d_in[10];
    const float* root1  = (const float*)d_in[11];
    const float* bias1  = (const float*)d_in[12];
    const float* We2    = (const float*)d_in[13];
    const float* be2    = (const float*)d_in[14];
    const float* root2  = (const float*)d_in[15];
    const float* bias2  = (const float*)d_in[16];
    const float* Wd1    = (const float*)d_in[17];
    const float* bd1    = (const float*)d_in[18];
    const float* Wd2    = (const float*)d_in[19];
    const float* bd2    = (const float*)d_in[20];
    const float* Wo     = (const float*)d_in[21];
    const float* bo     = (const float*)d_in[22];
    float* out = (float*)d_out;

    const int B = 256;
    const int CB = (EE + B - 1) / B;              // count blocks
    const int NB = (NN * 80 + B - 1) / B;         // nt1 blocks

    k_init     <<<(NN + B - 1) / B, B>>>();
    k_count_nt1<<<CB + NB, B>>>(ei, x, Wg1, We1, be1, CB);
    k_scan     <<<1, 1024>>>();
    k_scatter  <<<(EE + B - 1) / B, B>>>(ei, a_vals, efeat);
    k_agg1     <<<(NN * 16 + B - 1) / B, B>>>(x, b1, root1, bias1);
    k_nt2      <<<(NN * 160 + B - 1) / B, B>>>(Wg2, We2, be2);
    k_agg2_pool<<<(NN * 32 + B - 1) / B, B>>>(b2, root2, bias2, seg);
    k_head     <<<(GG + B - 1) / B, B>>>(Wd1, bd1, Wd2, bd2, Wo, bo, out);
}

// round 17
// speedup vs baseline: 1.7081x; 1.6552x over previous
#include <cuda_runtime.h>
#include <cuda_bf16.h>
#include <math.h>

#define NN 60000
#define EE 240000
#define FIN 10
#define SS 3
#define CC 16
#define GG 512

#define SCAN_B 256
#define SCAN_NBLK ((NN + SCAN_B - 1) / SCAN_B)   // 235

// ---------------- device scratch ----------------
__device__ int    g_cnt[NN];
__device__ int    g_rowptr[NN + 1];
__device__ int    g_cursor[NN];
__device__ int    g_blk[SCAN_NBLK];
__device__ int    g_col[EE];
__device__ float4 g_ef[EE];            // (a_val, e0, e1, e2) sorted by row
__device__ float  g_xw1[NN * 16];      // x @ W_gcn1
__device__ float  g_g1 [NN * 16];      // GCN layer-1 output
__device__ float  g_xw2[NN * 32];      // g1 @ W_gcn2
__device__ float  g_U1 [NN * 64];      // [n][s][16]
__device__ float  g_c1 [NN * 16];      // ECC layer-1 output
__device__ float  g_U2 [NN * 128];     // [n][s][32]
__device__ float  g_pool[GG * 64];     // [g][0:32]=GCN pool, [g][32:64]=ECC pool

// ---------------- init: zero cnt + pool; total edge count is constant ----------------
__global__ void k_init() {
    int i = blockIdx.x * blockDim.x + threadIdx.x;
    if (i < NN) g_cnt[i] = 0;
    if (i < GG * 64) g_pool[i] = 0.f;
    if (i == 0) g_rowptr[NN] = EE;
}

// ---------------- fused: edge count + layer-1 node transforms ----------------
__global__ void k_count_nt1(const int* __restrict__ ei,
                            const float* __restrict__ x,
                            const float* __restrict__ Wg1,
                            const float* __restrict__ We1,
                            const float* __restrict__ be1,
                            int CB) {
    if (blockIdx.x < CB) {
        int e = blockIdx.x * blockDim.x + threadIdx.x;
        if (e < EE) atomicAdd(&g_cnt[ei[e]], 1);
        return;
    }
    int tid = (blockIdx.x - CB) * blockDim.x + threadIdx.x;
    int n = tid / 80;
    int o = tid - n * 80;
    if (n >= NN) return;
    const float* xr = x + n * FIN;
    float acc = 0.f;
    if (o < 16) {
        #pragma unroll
        for (int f = 0; f < FIN; f++) acc += xr[f] * __ldg(&Wg1[f * 16 + o]);
        g_xw1[n * 16 + o] = acc;
    } else {
        int idx = o - 16;
        int s = idx >> 4;
        int oo = idx & 15;
        const float* w = (s == 0) ? be1 : (We1 + (s - 1) * (FIN * 16));
        #pragma unroll
        for (int f = 0; f < FIN; f++) acc += xr[f] * __ldg(&w[f * 16 + oo]);
        g_U1[n * 64 + idx] = acc;
    }
}

// ---------------- parallel scan, pass A: per-block exclusive scan + block totals ----------------
__global__ void k_scan_a() {
    int i = blockIdx.x * SCAN_B + threadIdx.x;
    int v = (i < NN) ? g_cnt[i] : 0;
    int lane = threadIdx.x & 31;
    int w = threadIdx.x >> 5;
    int s = v;
    #pragma unroll
    for (int o = 1; o < 32; o <<= 1) {
        int t = __shfl_up_sync(0xffffffffu, s, o);
        if (lane >= o) s += t;
    }
    __shared__ int wsum[8];
    if (lane == 31) wsum[w] = s;
    __syncthreads();
    if (w == 0 && lane < 8) {
        int t = wsum[lane];
        #pragma unroll
        for (int o = 1; o < 8; o <<= 1) {
            int u = __shfl_up_sync(0xffu, t, o);
            if (lane >= o) t += u;
        }
        wsum[lane] = t;
    }
    __syncthreads();
    int excl = s - v + (w > 0 ? wsum[w - 1] : 0);
    if (i < NN) g_rowptr[i] = excl;
    if (threadIdx.x == 0) g_blk[blockIdx.x] = wsum[7];
}

// ---------------- parallel scan, pass B: add block offsets, write cursor ----------------
__global__ void k_scan_b() {
    __shared__ int s_w[8];
    int b = blockIdx.x;
    int acc = 0;
    for (int k = threadIdx.x; k < b; k += SCAN_B) acc += g_blk[k];
    // block reduce
    int lane = threadIdx.x & 31;
    int w = threadIdx.x >> 5;
    #pragma unroll
    for (int o = 16; o > 0; o >>= 1) acc += __shfl_down_sync(0xffffffffu, acc, o);
    if (lane == 0) s_w[w] = acc;
    __syncthreads();
    if (threadIdx.x == 0) {
        int t = 0;
        #pragma unroll
        for (int k = 0; k < 8; k++) t += s_w[k];
        s_w[0] = t;
    }
    __syncthreads();
    int off = s_w[0];
    int i = b * SCAN_B + threadIdx.x;
    if (i < NN) {
        int r = g_rowptr[i] + off;
        g_rowptr[i] = r;
        g_cursor[i] = r;
    }
}

__global__ void k_scatter(const int* __restrict__ ei,
                          const float* __restrict__ a_vals,
                          const float* __restrict__ efeat) {
    int e = blockIdx.x * blockDim.x + threadIdx.x;
    if (e >= EE) return;
    int r = ei[e];
    int c = ei[EE + e];
    int pos = atomicAdd(&g_cursor[r], 1);
    g_col[pos] = c;
    g_ef[pos] = make_float4(a_vals[e], efeat[e * 3], efeat[e * 3 + 1], efeat[e * 3 + 2]);
}

// ---------------- fused layer-1 aggregation (GCN1 + ECC1) ----------------
__global__ void k_agg1(const float* __restrict__ x,
                       const float* __restrict__ b1,
                       const float* __restrict__ root1,
                       const float* __restrict__ bias1) {
    int tid = blockIdx.x * blockDim.x + threadIdx.x;
    int n = tid >> 4;
    int lane = tid & 15;
    if (n >= NN) return;
    int beg = g_rowptr[n], end = g_rowptr[n + 1];
    float ag = 0.f, ae = 0.f;
    int j = beg;
    for (; j + 1 < end; j += 2) {
        int c0 = g_col[j], c1 = g_col[j + 1];
        float4 f0 = g_ef[j], f1 = g_ef[j + 1];
        const float* u0 = g_U1 + (size_t)c0 * 64;
        const float* u1 = g_U1 + (size_t)c1 * 64;
        float x0 = g_xw1[(size_t)c0 * 16 + lane];
        float x1 = g_xw1[(size_t)c1 * 16 + lane];
        float v00 = u0[lane], v01 = u0[16 + lane], v02 = u0[32 + lane], v03 = u0[48 + lane];
        float v10 = u1[lane], v11 = u1[16 + lane], v12 = u1[32 + lane], v13 = u1[48 + lane];
        ag += f0.x * x0 + f1.x * x1;
        ae += v00 + f0.y * v01 + f0.z * v02 + f0.w * v03;
        ae += v10 + f1.y * v11 + f1.z * v12 + f1.w * v13;
    }
    if (j < end) {
        int c = g_col[j];
        float4 f = g_ef[j];
        const float* u = g_U1 + (size_t)c * 64;
        ag += f.x * g_xw1[(size_t)c * 16 + lane];
        ae += u[lane] + f.y * u[16 + lane] + f.z * u[32 + lane] + f.w * u[48 + lane];
    }
    float rt = 0.f;
    const float* xr = x + n * FIN;
    #pragma unroll
    for (int f = 0; f < FIN; f++) rt += xr[f] * __ldg(&root1[f * 16 + lane]);
    g_g1[n * 16 + lane] = fmaxf(ag + __ldg(&b1[lane]), 0.f);
    g_c1[n * 16 + lane] = fmaxf(ae + rt + __ldg(&bias1[lane]), 0.f);
}

// ---------------- layer-2 node transforms ----------------
__global__ void k_nt2(const float* __restrict__ Wg2,
                      const float* __restrict__ We2,
                      const float* __restrict__ be2) {
    int tid = blockIdx.x * blockDim.x + threadIdx.x;
    int n = tid / 160;
    int o = tid - n * 160;
    if (n >= NN) return;
    float acc = 0.f;
    if (o < 32) {
        const float* src = g_g1 + n * 16;
        #pragma unroll
        for (int f = 0; f < 16; f++) acc += src[f] * __ldg(&Wg2[f * 32 + o]);
        g_xw2[n * 32 + o] = acc;
    } else {
        int idx = o - 32;
        int s = idx >> 5;
        int oo = idx & 31;
        const float* w = (s == 0) ? be2 : (We2 + (s - 1) * (16 * 32));
        const float* src = g_c1 + n * 16;
        #pragma unroll
        for (int f = 0; f < 16; f++) acc += src[f] * __ldg(&w[f * 32 + oo]);
        g_U2[n * 128 + idx] = acc;
    }
}

// ---------------- fused layer-2 aggregation + pooling ----------------
__global__ void k_agg2_pool(const float* __restrict__ b2,
                            const float* __restrict__ root2,
                            const float* __restrict__ bias2,
                            const int* __restrict__ seg) {
    int tid = blockIdx.x * blockDim.x + threadIdx.x;
    int n = tid >> 5;
    int lane = tid & 31;
    if (n >= NN) return;
    int beg = g_rowptr[n], end = g_rowptr[n + 1];
    float ag = 0.f, ae = 0.f;
    int j = beg;
    for (; j + 1 < end; j += 2) {
        int c0 = g_col[j], c1 = g_col[j + 1];
        float4 f0 = g_ef[j], f1 = g_ef[j + 1];
        const float* u0 = g_U2 + (size_t)c0 * 128;
        const float* u1 = g_U2 + (size_t)c1 * 128;
        float x0 = g_xw2[(size_t)c0 * 32 + lane];
        float x1 = g_xw2[(size_t)c1 * 32 + lane];
        float v00 = u0[lane], v01 = u0[32 + lane], v02 = u0[64 + lane], v03 = u0[96 + lane];
        float v10 = u1[lane], v11 = u1[32 + lane], v12 = u1[64 + lane], v13 = u1[96 + lane];
        ag += f0.x * x0 + f1.x * x1;
        ae += v00 + f0.y * v01 + f0.z * v02 + f0.w * v03;
        ae += v10 + f1.y * v11 + f1.z * v12 + f1.w * v13;
    }
    if (j < end) {
        int c = g_col[j];
        float4 f = g_ef[j];
        const float* u = g_U2 + (size_t)c * 128;
        ag += f.x * g_xw2[(size_t)c * 32 + lane];
        ae += u[lane] + f.y * u[32 + lane] + f.z * u[64 + lane] + f.w * u[96 + lane];
    }
    float rt = 0.f;
    const float* cr = g_c1 + n * 16;
    #pragma unroll
    for (int f = 0; f < 16; f++) rt += cr[f] * __ldg(&root2[f * 32 + lane]);
    float vg = fmaxf(ag + __ldg(&b2[lane]), 0.f);
    float ve = fmaxf(ae + rt + __ldg(&bias2[lane]), 0.f);
    int gidx = seg[n] * 64;
    atomicAdd(&g_pool[gidx + lane], vg);
    atomicAdd(&g_pool[gidx + 32 + lane], ve);
}

// ---------------- MLP head ----------------
__global__ void k_head(const float* __restrict__ Wd1, const float* __restrict__ bd1,
                       const float* __restrict__ Wd2, const float* __restrict__ bd2,
                       const float* __restrict__ Wo,  const float* __restrict__ bo,
                       float* __restrict__ out) {
    int g = blockIdx.x * blockDim.x + threadIdx.x;
    if (g >= GG) return;
    float h[64];
    #pragma unroll
    for (int k = 0; k < 64; k++) h[k] = g_pool[g * 64 + k];
    float t1[16];
    #pragma unroll
    for (int c = 0; c < 16; c++) {
        float acc = __ldg(&bd1[c]);
        #pragma unroll
        for (int k = 0; k < 64; k++) acc += h[k] * __ldg(&Wd1[k * 16 + c]);
        t1[c] = fmaxf(acc, 0.f);
    }
    float t2[8];
    #pragma unroll
    for (int c = 0; c < 8; c++) {
        float acc = __ldg(&bd2[c]);
        #pragma unroll
        for (int k = 0; k < 16; k++) acc += t1[k] * __ldg(&Wd2[k * 8 + c]);
        t2[c] = fmaxf(acc, 0.f);
    }
    float o = __ldg(&bo[0]);
    #pragma unroll
    for (int k = 0; k < 8; k++) o += t2[k] * __ldg(&Wo[k]);
    out[g] = 1.f / (1.f + expf(-o));
}

// ---------------- launch ----------------
extern "C" void kernel_launch(void* const* d_in, const int* in_sizes, int n_in,
                              void* d_out, int out_size) {
    const float* x      = (const float*)d_in[0];
    const float* a_vals = (const float*)d_in[1];
    const float* efeat  = (const float*)d_in[2];
    const int*   ei     = (const int*)  d_in[3];
    const int*   seg    = (const int*)  d_in[4];
    const float* Wg1    = (const float*)d_in[5];
    const float* b1     = (const float*)d_in[6];
    const float* Wg2    = (const float*)d_in[7];
    const float* b2     = (const float*)d_in[8];
    const float* We1    = (const float*)d_in[9];
    const float* be1    = (const float*)d_in[10];
    const float* root1  = (const float*)d_in[11];
    const float* bias1  = (const float*)d_in[12];
    const float* We2    = (const float*)d_in[13];
    const float* be2    = (const float*)d_in[14];
    const float* root2  = (const float*)d_in[15];
    const float* bias2  = (const float*)d_in[16];
    const float* Wd1    = (const float*)d_in[17];
    const float* bd1    = (const float*)d_in[18];
    const float* Wd2    = (const float*)d_in[19];
    const float* bd2    = (const float*)d_in[20];
    const float* Wo     = (const float*)d_in[21];
    const float* bo     = (const float*)d_in[22];
    float* out = (float*)d_out;

    const int B = 256;
    const int CB = (EE + B - 1) / B;
    const int NB = (NN * 80 + B - 1) / B;

    k_init     <<<(NN + B - 1) / B, B>>>();
    k_count_nt1<<<CB + NB, B>>>(ei, x, Wg1, We1, be1, CB);
    k_scan_a   <<<SCAN_NBLK, SCAN_B>>>();
    k_scan_b   <<<SCAN_NBLK, SCAN_B>>>();
    k_scatter  <<<(EE + B - 1) / B, B>>>(ei, a_vals, efeat);
    k_agg1     <<<(NN * 16 + B - 1) / B, B>>>(x, b1, root1, bias1);
    k_nt2      <<<(NN * 160 + B - 1) / B, B>>>(Wg2, We2, be2);
    k_agg2_pool<<<(NN * 32 + B - 1) / B, B>>>(b2, root2, bias2, seg);
    k_head     <<<(GG + B - 1) / B, B>>>(Wd1, bd1, Wd2, bd2, Wo, bo, out);
}